// round 4
// baseline (speedup 1.0000x reference)
#include <cuda_runtime.h>
#include <math.h>

// Problem shape (fixed by the reference)
#define B 32
#define S 4096
#define H 768            // 768 floats = 6 float4 per lane across a warp
#define CHUNKS 16        // CTAs per batch in pass 1
#define WARPS 8          // warps per CTA
#define ROWS_PER_WARP (S / CHUNKS / WARPS)   // 32
#define NPART (B * CHUNKS * WARPS)           // 4096 warp partials

// Scratch for warp partials (allocation-free: __device__ globals)
__device__ float g_pm[NPART];
__device__ float g_pl[NPART];
__device__ float g_pacc[(size_t)NPART * H];   // 12.6 MB

// ---------------------------------------------------------------------------
// Pass 1: one-pass online softmax + weighted accumulate.
// Each warp streams ROWS_PER_WARP consecutive rows of one batch. The row is
// held in registers so the single HBM read feeds BOTH the q-dot and the
// exp-weighted accumulation.
// ---------------------------------------------------------------------------
__global__ __launch_bounds__(256, 2)
void attn_pass1(const float* __restrict__ hidden, const float* __restrict__ q)
{
    const int bx    = blockIdx.x;            // 0..511
    const int b     = bx >> 4;               // batch
    const int chunk = bx & 15;
    const int wid   = threadIdx.x >> 5;
    const int lane  = threadIdx.x & 31;

    const float4* qv4 = (const float4*)q;
    float4 qv[6];
#pragma unroll
    for (int i = 0; i < 6; i++) qv[i] = qv4[i * 32 + lane];

    const float* base = hidden + (size_t)b * S * H;
    const int row0 = chunk * (S / CHUNKS) + wid * ROWS_PER_WARP;

    float4 acc[6];
#pragma unroll
    for (int i = 0; i < 6; i++) acc[i] = make_float4(0.f, 0.f, 0.f, 0.f);
    float m = -INFINITY;
    float l = 0.f;

    // prefetch first row
    float4 x[6], xn[6];
    {
        const float4* rp = (const float4*)(base + (size_t)row0 * H);
#pragma unroll
        for (int i = 0; i < 6; i++) x[i] = rp[i * 32 + lane];
    }

    for (int r = 0; r < ROWS_PER_WARP; r++) {
        // prefetch next row (independent of the softmax chain below)
        if (r + 1 < ROWS_PER_WARP) {
            const float4* rp = (const float4*)(base + (size_t)(row0 + r + 1) * H);
#pragma unroll
            for (int i = 0; i < 6; i++) xn[i] = rp[i * 32 + lane];
        }

        // dot(hidden_row, q)
        float d = 0.f;
#pragma unroll
        for (int i = 0; i < 6; i++) {
            d = fmaf(x[i].x, qv[i].x, d);
            d = fmaf(x[i].y, qv[i].y, d);
            d = fmaf(x[i].z, qv[i].z, d);
            d = fmaf(x[i].w, qv[i].w, d);
        }
#pragma unroll
        for (int o = 16; o > 0; o >>= 1)
            d += __shfl_xor_sync(0xffffffffu, d, o);

        // online softmax update (warp-uniform m, l)
        if (d > m) {
            const float sc = __expf(m - d);   // exp(-inf) = 0 on first row
            l *= sc;
#pragma unroll
            for (int i = 0; i < 6; i++) {
                acc[i].x *= sc; acc[i].y *= sc; acc[i].z *= sc; acc[i].w *= sc;
            }
            m = d;
        }
        const float w = __expf(d - m);
        l += w;
#pragma unroll
        for (int i = 0; i < 6; i++) {
            acc[i].x = fmaf(w, x[i].x, acc[i].x);
            acc[i].y = fmaf(w, x[i].y, acc[i].y);
            acc[i].z = fmaf(w, x[i].z, acc[i].z);
            acc[i].w = fmaf(w, x[i].w, acc[i].w);
        }

#pragma unroll
        for (int i = 0; i < 6; i++) x[i] = xn[i];
    }

    const int gw = bx * WARPS + wid;         // batch-grouped: [b*128, b*128+128)
    if (lane == 0) { g_pm[gw] = m; g_pl[gw] = l; }
    float4* pa = (float4*)(g_pacc + (size_t)gw * H);
#pragma unroll
    for (int i = 0; i < 6; i++) pa[i * 32 + lane] = acc[i];
}

// ---------------------------------------------------------------------------
// Pass 2: combine the 128 warp partials of each batch.
// grid = 32 CTAs, 768 threads (one output element per thread).
// ---------------------------------------------------------------------------
__global__ __launch_bounds__(768)
void attn_combine(float* __restrict__ out)
{
    const int b = blockIdx.x;
    const int h = threadIdx.x;
    const int C = CHUNKS * WARPS;            // 128 partials per batch
    const int p0 = b * C;

    float M = -INFINITY;
#pragma unroll 4
    for (int c = 0; c < C; c++) M = fmaxf(M, g_pm[p0 + c]);

    float L = 0.f, r = 0.f;
#pragma unroll 4
    for (int c = 0; c < C; c++) {
        const float w = __expf(g_pm[p0 + c] - M);
        L = fmaf(w, g_pl[p0 + c], L);
        r = fmaf(w, g_pacc[(size_t)(p0 + c) * H + h], r);
    }
    out[b * H + h] = r / L;
}

extern "C" void kernel_launch(void* const* d_in, const int* in_sizes, int n_in,
                              void* d_out, int out_size)
{
    const float* hidden = (const float*)d_in[0];   // [32, 4096, 768] f32
    const float* querys = (const float*)d_in[1];   // [1, 768] f32
    float* out = (float*)d_out;                    // [32, 768] f32

    attn_pass1<<<B * CHUNKS, 256>>>(hidden, querys);
    attn_combine<<<B, H>>>(out);
}

// round 5
// speedup vs baseline: 1.2677x; 1.2677x over previous
#include <cuda_runtime.h>
#include <math.h>

// Problem shape (fixed by the reference)
#define B 32
#define S 4096
#define H 768            // 768 floats = 6 float4 per lane across a warp
#define CHUNKS 32        // CTAs per batch in pass 1
#define WARPS 8          // warps per CTA
#define ROWS_PER_WARP (S / CHUNKS / WARPS)   // 16
#define NPART (B * CHUNKS)                   // 1024 CTA-level partials

// Scratch for CTA partials (allocation-free: __device__ globals)
__device__ float g_pm[NPART];
__device__ float g_pl[NPART];
__device__ float g_pacc[(size_t)NPART * H];   // 3.1 MB

// ---------------------------------------------------------------------------
// Pass 1: one-pass online softmax + weighted accumulate.
// Each warp streams ROWS_PER_WARP consecutive rows of one batch; the row is
// held in registers so the single HBM read feeds BOTH the q-dot and the
// exp-weighted accumulation. The 8 warps of a CTA are then merged through
// shared memory so only ONE partial (m, l, acc[768]) per CTA hits DRAM.
// ---------------------------------------------------------------------------
__global__ __launch_bounds__(256, 2)
void attn_pass1(const float* __restrict__ hidden, const float* __restrict__ q)
{
    const int bx    = blockIdx.x;            // 0..1023
    const int b     = bx / CHUNKS;           // batch
    const int chunk = bx % CHUNKS;
    const int wid   = threadIdx.x >> 5;
    const int lane  = threadIdx.x & 31;

    const float4* qv4 = (const float4*)q;
    float4 qv[6];
#pragma unroll
    for (int i = 0; i < 6; i++) qv[i] = qv4[i * 32 + lane];

    const float* base = hidden + (size_t)b * S * H;
    const int row0 = chunk * (S / CHUNKS) + wid * ROWS_PER_WARP;

    float4 acc[6];
#pragma unroll
    for (int i = 0; i < 6; i++) acc[i] = make_float4(0.f, 0.f, 0.f, 0.f);
    float m = -INFINITY;
    float l = 0.f;

    // prefetch first row
    float4 x[6], xn[6];
    {
        const float4* rp = (const float4*)(base + (size_t)row0 * H);
#pragma unroll
        for (int i = 0; i < 6; i++) x[i] = rp[i * 32 + lane];
    }

    for (int r = 0; r < ROWS_PER_WARP; r++) {
        // prefetch next row (independent of the softmax chain below)
        if (r + 1 < ROWS_PER_WARP) {
            const float4* rp = (const float4*)(base + (size_t)(row0 + r + 1) * H);
#pragma unroll
            for (int i = 0; i < 6; i++) xn[i] = rp[i * 32 + lane];
        }

        // dot(hidden_row, q)
        float d = 0.f;
#pragma unroll
        for (int i = 0; i < 6; i++) {
            d = fmaf(x[i].x, qv[i].x, d);
            d = fmaf(x[i].y, qv[i].y, d);
            d = fmaf(x[i].z, qv[i].z, d);
            d = fmaf(x[i].w, qv[i].w, d);
        }
#pragma unroll
        for (int o = 16; o > 0; o >>= 1)
            d += __shfl_xor_sync(0xffffffffu, d, o);

        // online softmax update (warp-uniform m, l)
        if (d > m) {
            const float sc = __expf(m - d);   // exp(-inf) = 0 on first row
            l *= sc;
#pragma unroll
            for (int i = 0; i < 6; i++) {
                acc[i].x *= sc; acc[i].y *= sc; acc[i].z *= sc; acc[i].w *= sc;
            }
            m = d;
        }
        const float w = __expf(d - m);
        l += w;
#pragma unroll
        for (int i = 0; i < 6; i++) {
            acc[i].x = fmaf(w, x[i].x, acc[i].x);
            acc[i].y = fmaf(w, x[i].y, acc[i].y);
            acc[i].z = fmaf(w, x[i].z, acc[i].z);
            acc[i].w = fmaf(w, x[i].w, acc[i].w);
        }

#pragma unroll
        for (int i = 0; i < 6; i++) x[i] = xn[i];
    }

    // ---- CTA-level merge of the 8 warp partials through shared memory ----
    __shared__ float s_m[WARPS];
    __shared__ float s_l[WARPS];
    __shared__ float s_acc[WARPS][H];        // 24 KB

    if (lane == 0) { s_m[wid] = m; s_l[wid] = l; }
    {
        float4* sa = (float4*)s_acc[wid];
#pragma unroll
        for (int i = 0; i < 6; i++) sa[i * 32 + lane] = acc[i];
    }
    __syncthreads();

    float M = s_m[0];
#pragma unroll
    for (int w = 1; w < WARPS; w++) M = fmaxf(M, s_m[w]);

    float ws[WARPS];
#pragma unroll
    for (int w = 0; w < WARPS; w++) ws[w] = __expf(s_m[w] - M);

    // each thread owns 3 h-values (768 / 256); consecutive threads ->
    // consecutive smem addresses (conflict-free) and coalesced STG
    float* pa = g_pacc + (size_t)bx * H;
#pragma unroll
    for (int j = 0; j < 3; j++) {
        const int h = threadIdx.x + j * 256;
        float r = 0.f;
#pragma unroll
        for (int w = 0; w < WARPS; w++) r = fmaf(ws[w], s_acc[w][h], r);
        pa[h] = r;
    }
    if (threadIdx.x == 0) {
        float L = 0.f;
#pragma unroll
        for (int w = 0; w < WARPS; w++) L = fmaf(ws[w], s_l[w], L);
        g_pm[bx] = M;
        g_pl[bx] = L;
    }
}

// ---------------------------------------------------------------------------
// Pass 2: combine the 32 CTA partials of each batch.
// grid = 32 CTAs, 768 threads (one output element per thread).
// ---------------------------------------------------------------------------
__global__ __launch_bounds__(768)
void attn_combine(float* __restrict__ out)
{
    const int b = blockIdx.x;
    const int h = threadIdx.x;
    const int p0 = b * CHUNKS;

    float M = -INFINITY;
#pragma unroll
    for (int c = 0; c < CHUNKS; c++) M = fmaxf(M, g_pm[p0 + c]);

    float L = 0.f, r = 0.f;
#pragma unroll 8
    for (int c = 0; c < CHUNKS; c++) {
        const float w = __expf(g_pm[p0 + c] - M);
        L = fmaf(w, g_pl[p0 + c], L);
        r = fmaf(w, g_pacc[(size_t)(p0 + c) * H + h], r);
    }
    out[b * H + h] = r / L;
}

extern "C" void kernel_launch(void* const* d_in, const int* in_sizes, int n_in,
                              void* d_out, int out_size)
{
    const float* hidden = (const float*)d_in[0];   // [32, 4096, 768] f32
    const float* querys = (const float*)d_in[1];   // [1, 768] f32
    float* out = (float*)d_out;                    // [32, 768] f32

    attn_pass1<<<B * CHUNKS, 256>>>(hidden, querys);
    attn_combine<<<B, H>>>(out);
}

// round 6
// speedup vs baseline: 1.2719x; 1.0034x over previous
#include <cuda_runtime.h>
#include <math.h>

// Problem shape (fixed by the reference)
#define B 32
#define S 4096
#define H 768            // 768 floats = 6 float4 per lane across a warp
#define CHUNKS 32        // CTAs per batch in pass 1
#define WARPS 8          // warps per CTA
#define ROWS_PER_WARP (S / CHUNKS / WARPS)   // 16
#define NPART (B * CHUNKS)                   // 1024 CTA-level partials

// Scratch for CTA partials (allocation-free: __device__ globals)
__device__ float g_pm[NPART];
__device__ float g_pl[NPART];
__device__ float g_pacc[(size_t)NPART * H];   // 3.1 MB

// ---------------------------------------------------------------------------
// Pass 1: one-pass online softmax + weighted accumulate.
// Each warp streams ROWS_PER_WARP consecutive rows of one batch; the row is
// held in registers so the single HBM read feeds BOTH the q-dot and the
// exp-weighted accumulation. The 8 warps of a CTA are then merged through
// shared memory so only ONE partial (m, l, acc[768]) per CTA hits DRAM.
// ---------------------------------------------------------------------------
__global__ __launch_bounds__(256, 2)
void attn_pass1(const float* __restrict__ hidden, const float* __restrict__ q)
{
    const int bx    = blockIdx.x;            // 0..1023
    const int b     = bx / CHUNKS;           // batch
    const int chunk = bx % CHUNKS;
    const int wid   = threadIdx.x >> 5;
    const int lane  = threadIdx.x & 31;

    const float4* qv4 = (const float4*)q;
    float4 qv[6];
#pragma unroll
    for (int i = 0; i < 6; i++) qv[i] = qv4[i * 32 + lane];

    const float* base = hidden + (size_t)b * S * H;
    const int row0 = chunk * (S / CHUNKS) + wid * ROWS_PER_WARP;

    float4 acc[6];
#pragma unroll
    for (int i = 0; i < 6; i++) acc[i] = make_float4(0.f, 0.f, 0.f, 0.f);
    float m = -INFINITY;
    float l = 0.f;

    // prefetch first row
    float4 x[6], xn[6];
    {
        const float4* rp = (const float4*)(base + (size_t)row0 * H);
#pragma unroll
        for (int i = 0; i < 6; i++) x[i] = rp[i * 32 + lane];
    }

    for (int r = 0; r < ROWS_PER_WARP; r++) {
        // prefetch next row (independent of the softmax chain below)
        if (r + 1 < ROWS_PER_WARP) {
            const float4* rp = (const float4*)(base + (size_t)(row0 + r + 1) * H);
#pragma unroll
            for (int i = 0; i < 6; i++) xn[i] = rp[i * 32 + lane];
        }

        // dot(hidden_row, q)
        float d = 0.f;
#pragma unroll
        for (int i = 0; i < 6; i++) {
            d = fmaf(x[i].x, qv[i].x, d);
            d = fmaf(x[i].y, qv[i].y, d);
            d = fmaf(x[i].z, qv[i].z, d);
            d = fmaf(x[i].w, qv[i].w, d);
        }
#pragma unroll
        for (int o = 16; o > 0; o >>= 1)
            d += __shfl_xor_sync(0xffffffffu, d, o);

        // online softmax update (warp-uniform m, l)
        if (d > m) {
            const float sc = __expf(m - d);   // exp(-inf) = 0 on first row
            l *= sc;
#pragma unroll
            for (int i = 0; i < 6; i++) {
                acc[i].x *= sc; acc[i].y *= sc; acc[i].z *= sc; acc[i].w *= sc;
            }
            m = d;
        }
        const float w = __expf(d - m);
        l += w;
#pragma unroll
        for (int i = 0; i < 6; i++) {
            acc[i].x = fmaf(w, x[i].x, acc[i].x);
            acc[i].y = fmaf(w, x[i].y, acc[i].y);
            acc[i].z = fmaf(w, x[i].z, acc[i].z);
            acc[i].w = fmaf(w, x[i].w, acc[i].w);
        }

#pragma unroll
        for (int i = 0; i < 6; i++) x[i] = xn[i];
    }

    // ---- CTA-level merge of the 8 warp partials through shared memory ----
    __shared__ float s_m[WARPS];
    __shared__ float s_l[WARPS];
    __shared__ float s_acc[WARPS][H];        // 24 KB

    if (lane == 0) { s_m[wid] = m; s_l[wid] = l; }
    {
        float4* sa = (float4*)s_acc[wid];
#pragma unroll
        for (int i = 0; i < 6; i++) sa[i * 32 + lane] = acc[i];
    }
    __syncthreads();

    float M = s_m[0];
#pragma unroll
    for (int w = 1; w < WARPS; w++) M = fmaxf(M, s_m[w]);

    float ws[WARPS];
#pragma unroll
    for (int w = 0; w < WARPS; w++) ws[w] = __expf(s_m[w] - M);

    // each thread owns 3 h-values (768 / 256); consecutive threads ->
    // consecutive smem addresses (conflict-free) and coalesced STG
    float* pa = g_pacc + (size_t)bx * H;
#pragma unroll
    for (int j = 0; j < 3; j++) {
        const int h = threadIdx.x + j * 256;
        float r = 0.f;
#pragma unroll
        for (int w = 0; w < WARPS; w++) r = fmaf(ws[w], s_acc[w][h], r);
        pa[h] = r;
    }
    if (threadIdx.x == 0) {
        float L = 0.f;
#pragma unroll
        for (int w = 0; w < WARPS; w++) L = fmaf(ws[w], s_l[w], L);
        g_pm[bx] = M;
        g_pl[bx] = L;
    }
}

// ---------------------------------------------------------------------------
// Pass 2: combine the 32 CTA partials of each batch.
// grid = 32 CTAs, 768 threads (one output element per thread).
// ---------------------------------------------------------------------------
__global__ __launch_bounds__(768)
void attn_combine(float* __restrict__ out)
{
    const int b = blockIdx.x;
    const int h = threadIdx.x;
    const int p0 = b * CHUNKS;

    float M = -INFINITY;
#pragma unroll
    for (int c = 0; c < CHUNKS; c++) M = fmaxf(M, g_pm[p0 + c]);

    float L = 0.f, r = 0.f;
#pragma unroll 8
    for (int c = 0; c < CHUNKS; c++) {
        const float w = __expf(g_pm[p0 + c] - M);
        L = fmaf(w, g_pl[p0 + c], L);
        r = fmaf(w, g_pacc[(size_t)(p0 + c) * H + h], r);
    }
    out[b * H + h] = r / L;
}

extern "C" void kernel_launch(void* const* d_in, const int* in_sizes, int n_in,
                              void* d_out, int out_size)
{
    const float* hidden = (const float*)d_in[0];   // [32, 4096, 768] f32
    const float* querys = (const float*)d_in[1];   // [1, 768] f32
    float* out = (float*)d_out;                    // [32, 768] f32

    attn_pass1<<<B * CHUNKS, 256>>>(hidden, querys);
    attn_combine<<<B, H>>>(out);
}